// round 3
// baseline (speedup 1.0000x reference)
#include <cuda_runtime.h>
#include <math.h>

// Problem constants (fixed by the dataset)
#define NN   100000
#define EE   1600000
#define FDIM 64
#define FOUTL 40

// ---------------- static device scratch (no runtime allocation) -------------
__device__ int   g_counts[NN];
__device__ int   g_incl[NN];
__device__ int   g_partials[128];
__device__ int   g_row_ptr[NN + 1];
__device__ int   g_cursor[NN];
__device__ int   g_col_idx[EE];
__device__ float g_inv_deg[NN];
__device__ float g_agg[(size_t)NN * FDIM];
__device__ float g_h1[(size_t)NN * FDIM];
__device__ float g_h2[(size_t)NN * FDIM];

// ---------------- CSR construction ------------------------------------------

__global__ void k_zero_counts(int n) {
    int i = blockIdx.x * blockDim.x + threadIdx.x;
    if (i < n) g_counts[i] = 0;
}

__global__ void k_count(const int* __restrict__ er, int e) {
    int i = blockIdx.x * blockDim.x + threadIdx.x;
    if (i < e) atomicAdd(&g_counts[er[i]], 1);
}

// Block-level inclusive scan: 1024 elements per 256-thread block.
__global__ void k_scan1(int n) {
    __shared__ int wsums[8];
    int tid  = threadIdx.x;
    int base = blockIdx.x * 1024 + tid * 4;

    int v0 = 0, v1 = 0, v2 = 0, v3 = 0;
    if (base + 3 < n) {
        int4 c = *(const int4*)&g_counts[base];
        v0 = c.x; v1 = c.y; v2 = c.z; v3 = c.w;
    } else {
        if (base + 0 < n) v0 = g_counts[base + 0];
        if (base + 1 < n) v1 = g_counts[base + 1];
        if (base + 2 < n) v2 = g_counts[base + 2];
        if (base + 3 < n) v3 = g_counts[base + 3];
    }
    // thread-local inclusive
    v1 += v0; v2 += v1; v3 += v2;
    int s = v3;

    int lane = tid & 31, wid = tid >> 5;
    int x = s;
    #pragma unroll
    for (int d = 1; d < 32; d <<= 1) {
        int y = __shfl_up_sync(0xffffffffu, x, d);
        if (lane >= d) x += y;
    }
    if (lane == 31) wsums[wid] = x;
    __syncthreads();
    if (tid == 0) {
        int run = 0;
        #pragma unroll
        for (int i = 0; i < 8; i++) { run += wsums[i]; wsums[i] = run; }
    }
    __syncthreads();

    int prefix = (wid > 0 ? wsums[wid - 1] : 0) + (x - s);
    if (base + 3 < n) {
        int4 o; o.x = v0 + prefix; o.y = v1 + prefix; o.z = v2 + prefix; o.w = v3 + prefix;
        *(int4*)&g_incl[base] = o;
    } else {
        if (base + 0 < n) g_incl[base + 0] = v0 + prefix;
        if (base + 1 < n) g_incl[base + 1] = v1 + prefix;
        if (base + 2 < n) g_incl[base + 2] = v2 + prefix;
        if (base + 3 < n) g_incl[base + 3] = v3 + prefix;
    }
    if (tid == 0) g_partials[blockIdx.x] = wsums[7];
}

// Scan the (<=128) block partials; nb = number of scan1 blocks.
__global__ void k_scan2(int nb) {
    __shared__ int sh[128];
    int tid = threadIdx.x;
    sh[tid] = (tid < nb) ? g_partials[tid] : 0;
    __syncthreads();
    if (tid == 0) {
        int run = 0;
        for (int i = 0; i < nb; i++) { run += sh[i]; sh[i] = run; }
    }
    __syncthreads();
    if (tid < nb) g_partials[tid] = sh[tid];
}

__global__ void k_finalize(int n) {
    int i = blockIdx.x * blockDim.x + threadIdx.x;
    if (i >= n) return;
    int b   = i >> 10;
    int off = (b > 0) ? g_partials[b - 1] : 0;
    int inc = g_incl[i] + off;
    int cnt = g_counts[i];
    g_row_ptr[i + 1] = inc;
    g_cursor[i]      = inc - cnt;
    g_inv_deg[i]     = (cnt > 0) ? (1.0f / (float)cnt) : 0.0f;
    if (i == 0) g_row_ptr[0] = 0;
}

__global__ void k_fill(const int* __restrict__ er, const int* __restrict__ ec, int e) {
    int i = blockIdx.x * blockDim.x + threadIdx.x;
    if (i < e) {
        int r   = er[i];
        int pos = atomicAdd(&g_cursor[r], 1);
        g_col_idx[pos] = ec[i];
    }
}

// ---------------- Aggregation: one warp per row, 4-way edge unroll -----------
// Lane holds float2 of the 64-wide feature row -> 2x128B coalesced per neighbor.
// 4 neighbors in flight (8 independent float2 gathers) AND independent
// accumulator pairs per unroll slot: each group's FADDs retire against their
// own chain, so the loop is bound by load completion, not the FADD chain.
__global__ void __launch_bounds__(256)
k_aggregate(const float* __restrict__ act, int n) {
    int warp = (blockIdx.x * blockDim.x + threadIdx.x) >> 5;
    int lane = threadIdx.x & 31;
    if (warp >= n) return;
    int start = g_row_ptr[warp];
    int end   = g_row_ptr[warp + 1];

    float p0 = 0.0f, p1 = 0.0f, q0 = 0.0f, q1 = 0.0f;
    float r0 = 0.0f, r1 = 0.0f, t0 = 0.0f, t1 = 0.0f;
    int e = start;
    for (; e + 4 <= end; e += 4) {
        int j0 = g_col_idx[e + 0];
        int j1 = g_col_idx[e + 1];
        int j2 = g_col_idx[e + 2];
        int j3 = g_col_idx[e + 3];
        float2 a0 = __ldg(((const float2*)(act + (size_t)j0 * FDIM)) + lane);
        float2 a1 = __ldg(((const float2*)(act + (size_t)j1 * FDIM)) + lane);
        float2 a2 = __ldg(((const float2*)(act + (size_t)j2 * FDIM)) + lane);
        float2 a3 = __ldg(((const float2*)(act + (size_t)j3 * FDIM)) + lane);
        p0 += a0.x; p1 += a0.y;
        q0 += a1.x; q1 += a1.y;
        r0 += a2.x; r1 += a2.y;
        t0 += a3.x; t1 += a3.y;
    }
    for (; e < end; e++) {
        int j = g_col_idx[e];
        float2 a = __ldg(((const float2*)(act + (size_t)j * FDIM)) + lane);
        p0 += a.x; p1 += a.y;
    }
    float s0 = (p0 + q0) + (r0 + t0);
    float s1 = (p1 + q1) + (r1 + t1);

    float inv = g_inv_deg[warp];
    float2 o; o.x = s0 * inv; o.y = s1 * inv;
    ((float2*)(g_agg + (size_t)warp * FDIM))[lane] = o;
}

// ---------------- Fused dual-GEMM (+bias, relu / log_softmax) ----------------
// out[r] = agg[r]@Wl + bl + act[r]@Wr + br ; thread-per-row, W staged in smem.
template <int FO, bool RELU, bool LSM>
__global__ void __launch_bounds__(256)
k_gemm(const float* __restrict__ act,
       const float* __restrict__ Wl, const float* __restrict__ bl,
       const float* __restrict__ Wr, const float* __restrict__ br,
       float* __restrict__ out, int n) {
    __shared__ float sWl[FDIM * FO];
    __shared__ float sWr[FDIM * FO];
    __shared__ float sb[FO];
    for (int i = threadIdx.x; i < FDIM * FO; i += 256) {
        sWl[i] = Wl[i];
        sWr[i] = Wr[i];
    }
    for (int i = threadIdx.x; i < FO; i += 256) sb[i] = bl[i] + br[i];
    __syncthreads();

    int row = blockIdx.x * 256 + threadIdx.x;
    if (row >= n) return;

    float acc[FO];
    #pragma unroll
    for (int o = 0; o < FO; o++) acc[o] = sb[o];

    const float4* ap = (const float4*)(g_agg + (size_t)row * FDIM);
    const float4* xp = (const float4*)(act   + (size_t)row * FDIM);

    #pragma unroll 1
    for (int kc = 0; kc < FDIM / 4; kc++) {
        float4 a = ap[kc];
        float4 x = xp[kc];
        float av[4] = {a.x, a.y, a.z, a.w};
        float xv[4] = {x.x, x.y, x.z, x.w};
        #pragma unroll
        for (int t = 0; t < 4; t++) {
            int k = kc * 4 + t;
            const float4* wl4 = (const float4*)&sWl[k * FO];
            const float4* wr4 = (const float4*)&sWr[k * FO];
            #pragma unroll
            for (int o4 = 0; o4 < FO / 4; o4++) {
                float4 wl = wl4[o4];
                float4 wr = wr4[o4];
                acc[o4 * 4 + 0] += av[t] * wl.x + xv[t] * wr.x;
                acc[o4 * 4 + 1] += av[t] * wl.y + xv[t] * wr.y;
                acc[o4 * 4 + 2] += av[t] * wl.z + xv[t] * wr.z;
                acc[o4 * 4 + 3] += av[t] * wl.w + xv[t] * wr.w;
            }
        }
    }

    if (LSM) {
        float m = acc[0];
        #pragma unroll
        for (int o = 1; o < FO; o++) m = fmaxf(m, acc[o]);
        float sum = 0.0f;
        #pragma unroll
        for (int o = 0; o < FO; o++) sum += __expf(acc[o] - m);
        float lse = m + __logf(sum);
        float* op = out + (size_t)row * FO;
        #pragma unroll
        for (int o4 = 0; o4 < FO / 4; o4++) {
            float4 v;
            v.x = acc[o4 * 4 + 0] - lse;
            v.y = acc[o4 * 4 + 1] - lse;
            v.z = acc[o4 * 4 + 2] - lse;
            v.w = acc[o4 * 4 + 3] - lse;
            ((float4*)op)[o4] = v;
        }
    } else {
        float* op = out + (size_t)row * FO;
        #pragma unroll
        for (int o4 = 0; o4 < FO / 4; o4++) {
            float4 v;
            v.x = acc[o4 * 4 + 0];
            v.y = acc[o4 * 4 + 1];
            v.z = acc[o4 * 4 + 2];
            v.w = acc[o4 * 4 + 3];
            if (RELU) {
                v.x = fmaxf(v.x, 0.0f); v.y = fmaxf(v.y, 0.0f);
                v.z = fmaxf(v.z, 0.0f); v.w = fmaxf(v.w, 0.0f);
            }
            ((float4*)op)[o4] = v;
        }
    }
}

// ---------------- launch ------------------------------------------------------
extern "C" void kernel_launch(void* const* d_in, const int* in_sizes, int n_in,
                              void* d_out, int out_size) {
    const float* x   = (const float*)d_in[0];
    const int*   er  = (const int*)d_in[1];
    const int*   ec  = (const int*)d_in[2];
    // d_in[3], d_in[4]: chunking scalars, unused (identity in eval path)
    const float* Wl0 = (const float*)d_in[5];
    const float* bl0 = (const float*)d_in[6];
    const float* Wr0 = (const float*)d_in[7];
    const float* br0 = (const float*)d_in[8];
    const float* Wl1 = (const float*)d_in[9];
    const float* bl1 = (const float*)d_in[10];
    const float* Wr1 = (const float*)d_in[11];
    const float* br1 = (const float*)d_in[12];
    const float* Wl2 = (const float*)d_in[13];
    const float* bl2 = (const float*)d_in[14];
    const float* Wr2 = (const float*)d_in[15];
    const float* br2 = (const float*)d_in[16];
    float* out = (float*)d_out;

    int n = in_sizes[0] / FDIM;   // 100000
    int e = in_sizes[1];          // 1600000
    if (n > NN) n = NN;
    if (e > EE) e = EE;

    int nb_n   = (n + 255) / 256;
    int nb_e   = (e + 255) / 256;
    int nb_sc  = (n + 1023) / 1024;
    int nb_agg = ((n * 32) + 255) / 256;

    // ---- CSR build (recomputed every launch; deterministic work) ----
    k_zero_counts<<<nb_n, 256>>>(n);
    k_count<<<nb_e, 256>>>(er, e);
    k_scan1<<<nb_sc, 256>>>(n);
    k_scan2<<<1, 128>>>(nb_sc);
    k_finalize<<<nb_n, 256>>>(n);
    k_fill<<<nb_e, 256>>>(er, ec, e);

    // ---- Layer 0: x -> h1 (relu) ----
    k_aggregate<<<nb_agg, 256>>>(x, n);
    k_gemm<FDIM, true, false><<<nb_n, 256>>>(x, Wl0, bl0, Wr0, br0, g_h1, n);

    // ---- Layer 1: h1 -> h2 (relu) ----
    k_aggregate<<<nb_agg, 256>>>(g_h1, n);
    k_gemm<FDIM, true, false><<<nb_n, 256>>>(g_h1, Wl1, bl1, Wr1, br1, g_h2, n);

    // ---- Layer 2: h2 -> out (fused log_softmax) ----
    k_aggregate<<<nb_agg, 256>>>(g_h2, n);
    k_gemm<FOUTL, false, true><<<nb_n, 256>>>(g_h2, Wl2, bl2, Wr2, br2, out, n);
}

// round 8
// speedup vs baseline: 1.1848x; 1.1848x over previous
#include <cuda_runtime.h>
#include <math.h>

// Problem constants (fixed by the dataset)
#define NN   100000
#define EE   1600000
#define FDIM 64
#define FOUTL 40

// ---------------- static device scratch (no runtime allocation) -------------
__device__ int   g_counts[NN];
__device__ int   g_incl[NN];
__device__ int   g_partials[128];
__device__ int   g_row_ptr[NN + 1];
__device__ int   g_cursor[NN];
__device__ int   g_col_idx[EE];
__device__ float g_inv_deg[NN];
__device__ float g_agg[(size_t)NN * FDIM];
__device__ float g_h1[(size_t)NN * FDIM];
__device__ float g_h2[(size_t)NN * FDIM];

// f32x2 packed FMA helpers (sm_103a: fma.rn.f32x2 only reachable via PTX)
__device__ __forceinline__ unsigned long long pack2(float lo, float hi) {
    unsigned long long r;
    asm("mov.b64 %0, {%1, %2};" : "=l"(r) : "f"(lo), "f"(hi));
    return r;
}
__device__ __forceinline__ void unpack2(unsigned long long v, float& lo, float& hi) {
    asm("mov.b64 {%0, %1}, %2;" : "=f"(lo), "=f"(hi) : "l"(v));
}
__device__ __forceinline__ void ffma2(unsigned long long& d, unsigned long long a,
                                      unsigned long long b) {
    asm("fma.rn.f32x2 %0, %1, %2, %0;" : "+l"(d) : "l"(a), "l"(b));
}

// ---------------- CSR construction ------------------------------------------

__global__ void k_zero_counts(int n) {
    int i = blockIdx.x * blockDim.x + threadIdx.x;
    if (i < n) g_counts[i] = 0;
}

__global__ void k_count(const int* __restrict__ er, int e) {
    int i = blockIdx.x * blockDim.x + threadIdx.x;
    if (i < e) atomicAdd(&g_counts[er[i]], 1);
}

// Block-level inclusive scan: 1024 elements per 256-thread block.
// Writes per-block totals (raw, unscanned) to g_partials.
__global__ void k_scan1(int n) {
    __shared__ int wsums[8];
    int tid  = threadIdx.x;
    int base = blockIdx.x * 1024 + tid * 4;

    int v0 = 0, v1 = 0, v2 = 0, v3 = 0;
    if (base + 3 < n) {
        int4 c = *(const int4*)&g_counts[base];
        v0 = c.x; v1 = c.y; v2 = c.z; v3 = c.w;
    } else {
        if (base + 0 < n) v0 = g_counts[base + 0];
        if (base + 1 < n) v1 = g_counts[base + 1];
        if (base + 2 < n) v2 = g_counts[base + 2];
        if (base + 3 < n) v3 = g_counts[base + 3];
    }
    v1 += v0; v2 += v1; v3 += v2;
    int s = v3;

    int lane = tid & 31, wid = tid >> 5;
    int x = s;
    #pragma unroll
    for (int d = 1; d < 32; d <<= 1) {
        int y = __shfl_up_sync(0xffffffffu, x, d);
        if (lane >= d) x += y;
    }
    if (lane == 31) wsums[wid] = x;
    __syncthreads();
    if (tid == 0) {
        int run = 0;
        #pragma unroll
        for (int i = 0; i < 8; i++) { run += wsums[i]; wsums[i] = run; }
    }
    __syncthreads();

    int prefix = (wid > 0 ? wsums[wid - 1] : 0) + (x - s);
    if (base + 3 < n) {
        int4 o; o.x = v0 + prefix; o.y = v1 + prefix; o.z = v2 + prefix; o.w = v3 + prefix;
        *(int4*)&g_incl[base] = o;
    } else {
        if (base + 0 < n) g_incl[base + 0] = v0 + prefix;
        if (base + 1 < n) g_incl[base + 1] = v1 + prefix;
        if (base + 2 < n) g_incl[base + 2] = v2 + prefix;
        if (base + 3 < n) g_incl[base + 3] = v3 + prefix;
    }
    if (tid == 0) g_partials[blockIdx.x] = wsums[7];
}

// Finalize: every block re-scans the (<=128) partials locally (cheap), then
// computes row_ptr / cursor / inv_deg. Replaces the old separate k_scan2.
__global__ void k_finalize(int n, int nb) {
    __shared__ int sp[128];
    if (threadIdx.x < 128) sp[threadIdx.x] = (threadIdx.x < nb) ? g_partials[threadIdx.x] : 0;
    __syncthreads();
    if (threadIdx.x == 0) {
        int run = 0;
        for (int i = 0; i < nb; i++) { run += sp[i]; sp[i] = run; }
    }
    __syncthreads();

    int i = blockIdx.x * blockDim.x + threadIdx.x;
    if (i >= n) return;
    int b   = i >> 10;
    int off = (b > 0) ? sp[b - 1] : 0;
    int inc = g_incl[i] + off;
    int cnt = g_counts[i];
    g_row_ptr[i + 1] = inc;
    g_cursor[i]      = inc - cnt;
    g_inv_deg[i]     = (cnt > 0) ? (1.0f / (float)cnt) : 0.0f;
    if (i == 0) g_row_ptr[0] = 0;
}

__global__ void k_fill(const int* __restrict__ er, const int* __restrict__ ec, int e) {
    int i = blockIdx.x * blockDim.x + threadIdx.x;
    if (i < e) {
        int r   = er[i];
        int pos = atomicAdd(&g_cursor[r], 1);
        g_col_idx[pos] = ec[i];
    }
}

// ---------------- Aggregation: warp per row, shfl-batched indices ------------
// One coalesced LDG fetches up to 32 col indices for the whole warp; indices
// are then broadcast via shfl (26 cyc, register-resident) instead of scalar
// memory loads. All gathers of a batch are address-independent -> MLP ~16-32,
// attacking the latency-serialization hypothesis directly.
__global__ void __launch_bounds__(256)
k_aggregate(const float* __restrict__ act, int n) {
    int warp = (blockIdx.x * blockDim.x + threadIdx.x) >> 5;
    int lane = threadIdx.x & 31;
    if (warp >= n) return;
    int start = g_row_ptr[warp];
    int end   = g_row_ptr[warp + 1];

    float p0 = 0.0f, p1 = 0.0f, q0 = 0.0f, q1 = 0.0f;
    float r0 = 0.0f, r1 = 0.0f, u0 = 0.0f, u1 = 0.0f;

    for (int base = start; base < end; base += 32) {
        int idx = 0;
        if (base + lane < end) idx = g_col_idx[base + lane];   // one coalesced LDG
        int m = end - base; if (m > 32) m = 32;

        int t = 0;
        for (; t + 4 <= m; t += 4) {
            int j0 = __shfl_sync(0xffffffffu, idx, t + 0);
            int j1 = __shfl_sync(0xffffffffu, idx, t + 1);
            int j2 = __shfl_sync(0xffffffffu, idx, t + 2);
            int j3 = __shfl_sync(0xffffffffu, idx, t + 3);
            float2 a0 = __ldg(((const float2*)(act + (size_t)j0 * FDIM)) + lane);
            float2 a1 = __ldg(((const float2*)(act + (size_t)j1 * FDIM)) + lane);
            float2 a2 = __ldg(((const float2*)(act + (size_t)j2 * FDIM)) + lane);
            float2 a3 = __ldg(((const float2*)(act + (size_t)j3 * FDIM)) + lane);
            p0 += a0.x; p1 += a0.y;
            q0 += a1.x; q1 += a1.y;
            r0 += a2.x; r1 += a2.y;
            u0 += a3.x; u1 += a3.y;
        }
        for (; t < m; t++) {
            int j = __shfl_sync(0xffffffffu, idx, t);
            float2 a = __ldg(((const float2*)(act + (size_t)j * FDIM)) + lane);
            p0 += a.x; p1 += a.y;
        }
    }
    float s0 = (p0 + q0) + (r0 + u0);
    float s1 = (p1 + q1) + (r1 + u1);

    float inv = g_inv_deg[warp];
    float2 o; o.x = s0 * inv; o.y = s1 * inv;
    ((float2*)(g_agg + (size_t)warp * FDIM))[lane] = o;
}

// ---------------- Fused dual-GEMM (+bias, relu / log_softmax), f32x2 ---------
// out[r] = agg[r]@Wl + bl + act[r]@Wr + br ; thread-per-row, W staged in smem.
// Accumulators are packed f32x2 -> FMA issue count halved vs scalar FFMA.
template <int FO, bool RELU, bool LSM>
__global__ void __launch_bounds__(256)
k_gemm(const float* __restrict__ act,
       const float* __restrict__ Wl, const float* __restrict__ bl,
       const float* __restrict__ Wr, const float* __restrict__ br,
       float* __restrict__ out, int n) {
    __shared__ float sWl[FDIM * FO];
    __shared__ float sWr[FDIM * FO];
    __shared__ float sb[FO];
    for (int i = threadIdx.x; i < FDIM * FO; i += 256) {
        sWl[i] = Wl[i];
        sWr[i] = Wr[i];
    }
    for (int i = threadIdx.x; i < FO; i += 256) sb[i] = bl[i] + br[i];
    __syncthreads();

    int row = blockIdx.x * 256 + threadIdx.x;
    if (row >= n) return;

    unsigned long long acc[FO / 2];
    #pragma unroll
    for (int o2 = 0; o2 < FO / 2; o2++) acc[o2] = pack2(sb[2 * o2], sb[2 * o2 + 1]);

    const float4* ap = (const float4*)(g_agg + (size_t)row * FDIM);
    const float4* xp = (const float4*)(act   + (size_t)row * FDIM);

    #pragma unroll 1
    for (int kc = 0; kc < FDIM / 4; kc++) {
        float4 a = ap[kc];
        float4 x = xp[kc];
        float av[4] = {a.x, a.y, a.z, a.w};
        float xv[4] = {x.x, x.y, x.z, x.w};
        #pragma unroll
        for (int t = 0; t < 4; t++) {
            int k = kc * 4 + t;
            unsigned long long av2 = pack2(av[t], av[t]);
            unsigned long long xv2 = pack2(xv[t], xv[t]);
            const ulonglong2* wl4 = (const ulonglong2*)&sWl[k * FO];
            const ulonglong2* wr4 = (const ulonglong2*)&sWr[k * FO];
            #pragma unroll
            for (int o4 = 0; o4 < FO / 4; o4++) {
                ulonglong2 wl = wl4[o4];       // LDS.128 -> two f32x2 lanes
                ulonglong2 wr = wr4[o4];
                ffma2(acc[2 * o4 + 0], av2, wl.x);
                ffma2(acc[2 * o4 + 1], av2, wl.y);
                ffma2(acc[2 * o4 + 0], xv2, wr.x);
                ffma2(acc[2 * o4 + 1], xv2, wr.y);
            }
        }
    }

    float accf[FO];
    #pragma unroll
    for (int o2 = 0; o2 < FO / 2; o2++) unpack2(acc[o2], accf[2 * o2], accf[2 * o2 + 1]);

    if (LSM) {
        float m = accf[0];
        #pragma unroll
        for (int o = 1; o < FO; o++) m = fmaxf(m, accf[o]);
        float sum = 0.0f;
        #pragma unroll
        for (int o = 0; o < FO; o++) sum += __expf(accf[o] - m);
        float lse = m + __logf(sum);
        float* op = out + (size_t)row * FO;
        #pragma unroll
        for (int o4 = 0; o4 < FO / 4; o4++) {
            float4 v;
            v.x = accf[o4 * 4 + 0] - lse;
            v.y = accf[o4 * 4 + 1] - lse;
            v.z = accf[o4 * 4 + 2] - lse;
            v.w = accf[o4 * 4 + 3] - lse;
            ((float4*)op)[o4] = v;
        }
    } else {
        float* op = out + (size_t)row * FO;
        #pragma unroll
        for (int o4 = 0; o4 < FO / 4; o4++) {
            float4 v;
            v.x = accf[o4 * 4 + 0];
            v.y = accf[o4 * 4 + 1];
            v.z = accf[o4 * 4 + 2];
            v.w = accf[o4 * 4 + 3];
            if (RELU) {
                v.x = fmaxf(v.x, 0.0f); v.y = fmaxf(v.y, 0.0f);
                v.z = fmaxf(v.z, 0.0f); v.w = fmaxf(v.w, 0.0f);
            }
            ((float4*)op)[o4] = v;
        }
    }
}

// ---------------- launch ------------------------------------------------------
extern "C" void kernel_launch(void* const* d_in, const int* in_sizes, int n_in,
                              void* d_out, int out_size) {
    const float* x   = (const float*)d_in[0];
    const int*   er  = (const int*)d_in[1];
    const int*   ec  = (const int*)d_in[2];
    // d_in[3], d_in[4]: chunking scalars, unused (identity in eval path)
    const float* Wl0 = (const float*)d_in[5];
    const float* bl0 = (const float*)d_in[6];
    const float* Wr0 = (const float*)d_in[7];
    const float* br0 = (const float*)d_in[8];
    const float* Wl1 = (const float*)d_in[9];
    const float* bl1 = (const float*)d_in[10];
    const float* Wr1 = (const float*)d_in[11];
    const float* br1 = (const float*)d_in[12];
    const float* Wl2 = (const float*)d_in[13];
    const float* bl2 = (const float*)d_in[14];
    const float* Wr2 = (const float*)d_in[15];
    const float* br2 = (const float*)d_in[16];
    float* out = (float*)d_out;

    int n = in_sizes[0] / FDIM;   // 100000
    int e = in_sizes[1];          // 1600000
    if (n > NN) n = NN;
    if (e > EE) e = EE;

    int nb_n   = (n + 255) / 256;
    int nb_e   = (e + 255) / 256;
    int nb_sc  = (n + 1023) / 1024;
    int nb_agg = ((n * 32) + 255) / 256;

    // ---- CSR build (recomputed every launch; deterministic work) ----
    k_zero_counts<<<nb_n, 256>>>(n);                 // launch 0
    k_count<<<nb_e, 256>>>(er, e);                   // launch 1
    k_scan1<<<nb_sc, 256>>>(n);                      // launch 2
    k_finalize<<<nb_n, 256>>>(n, nb_sc);             // launch 3 (scan2 fused in)
    k_fill<<<nb_e, 256>>>(er, ec, e);                // launch 4

    // ---- Layer 0: x -> h1 (relu) ----
    k_aggregate<<<nb_agg, 256>>>(x, n);              // launch 5 (ncu -s 5 target)
    k_gemm<FDIM, true, false><<<nb_n, 256>>>(x, Wl0, bl0, Wr0, br0, g_h1, n);

    // ---- Layer 1: h1 -> h2 (relu) ----
    k_aggregate<<<nb_agg, 256>>>(g_h1, n);
    k_gemm<FDIM, true, false><<<nb_n, 256>>>(g_h1, Wl1, bl1, Wr1, br1, g_h2, n);

    // ---- Layer 2: h2 -> out (fused log_softmax) ----
    k_aggregate<<<nb_agg, 256>>>(g_h2, n);
    k_gemm<FOUTL, false, true><<<nb_n, 256>>>(g_h2, Wl2, bl2, Wr2, br2, out, n);
}